// round 13
// baseline (speedup 1.0000x reference)
#include <cuda_runtime.h>
#include <cstdint>
#include <math_constants.h>

#define N_SPLINES 64
#define C_DIM     64
#define T_DIM     68
#define NJ        67
#define DMAX      68           // breakpoints = distinct knot values <= 68
#define NTHD      75           // T array: [0]=-INF, [1..D], [D+1..74]=+INF
#define NPFD      71           // prefix polys m = 0..70 (m <= 68 used)
#define NB        512          // buckets, width 1/64 over [-4,4)

// Precomputed tables, TRANSPOSED in gmem for coalesced smem fill
__device__ float   g_thT[NTHD][N_SPLINES];
__device__ float4  g_CT [NPFD][N_SPLINES];
__device__ uint8_t g_btT[NB][N_SPLINES];

// ---------------------------------------------------------------------------
// Precompute (fp64), level-parallel. Prefix poly at breakpoint X:
//   P_X = sum_j [t_j <= X < max(t_j,t_{j+1})] * Q_j
// built by 4 threads per m (j strided mod 4) + shuffle reduce -> chain depth 17.
// ---------------------------------------------------------------------------
__device__ __forceinline__ double sinv(double den) {
    return den == 0.0 ? 0.0 : 1.0 / den;
}

__global__ void precompute_kernel(const float* __restrict__ t,
                                  const float* __restrict__ c) {
    const int s   = blockIdx.x;
    const int tid = threadIdx.x;

    __shared__ double st[T_DIM];
    __shared__ double sc[C_DIM];
    __shared__ double inv1[67], inv2[66], inv3[65];
    __shared__ double p1[66][2][2];
    __shared__ double p2[65][3][3];
    __shared__ double p3[64][4][4];
    __shared__ double qm[NJ][4];       // monomial Q_j
    __shared__ float  kf[T_DIM];       // fp32 knots (original order)
    __shared__ float  vmax[NJ];        // max(t_j, t_{j+1})
    __shared__ float  skf[T_DIM];      // sorted knots
    __shared__ int    dfl[T_DIM];      // distinct flags -> inclusive scan
    __shared__ float  dval[T_DIM];     // distinct sorted knot values

    if (tid < T_DIM) {
        float kv = t[s * T_DIM + tid];
        kf[tid] = kv;
        st[tid] = (double)kv;
    }
    if (tid < C_DIM) sc[tid] = (double)c[s * C_DIM + tid];
    __syncthreads();

    // L0: reciprocal gaps
    if (tid < 67) inv1[tid] = sinv(st[tid + 1] - st[tid]);
    else if (tid < 133) { int a = tid - 67; inv2[a] = sinv(st[a + 2] - st[a]); }
    else if (tid < 198) { int a = tid - 133; inv3[a] = sinv(st[a + 3] - st[a]); }
    __syncthreads();

    // L1
    if (tid < 66) {
        int a = tid;
        p1[a][0][0] = -st[a] * inv1[a];        p1[a][0][1] = inv1[a];
        p1[a][1][0] = st[a + 2] * inv1[a + 1]; p1[a][1][1] = -inv1[a + 1];
    }
    __syncthreads();

    // L2
    if (tid < 65) {
        int a = tid;
        double l0 = -st[a] * inv2[a],        l1 = inv2[a];
        double r0 = st[a + 3] * inv2[a + 1], r1 = -inv2[a + 1];
        double o[3][3];
#pragma unroll
        for (int jj = 0; jj < 3; ++jj)
#pragma unroll
            for (int d = 0; d < 3; ++d) o[jj][d] = 0.0;
#pragma unroll
        for (int jj = 0; jj < 2; ++jj)
#pragma unroll
            for (int d = 0; d < 2; ++d) {
                o[jj][d]     += l0 * p1[a][jj][d];
                o[jj][d + 1] += l1 * p1[a][jj][d];
            }
#pragma unroll
        for (int jj = 1; jj < 3; ++jj)
#pragma unroll
            for (int d = 0; d < 2; ++d) {
                o[jj][d]     += r0 * p1[a + 1][jj - 1][d];
                o[jj][d + 1] += r1 * p1[a + 1][jj - 1][d];
            }
#pragma unroll
        for (int jj = 0; jj < 3; ++jj)
#pragma unroll
            for (int d = 0; d < 3; ++d) p2[a][jj][d] = o[jj][d];
    }
    __syncthreads();

    // L3
    if (tid < 64) {
        int i = tid;
        double l0 = -st[i] * inv3[i],        l1 = inv3[i];
        double r0 = st[i + 4] * inv3[i + 1], r1 = -inv3[i + 1];
        double o[4][4];
#pragma unroll
        for (int jj = 0; jj < 4; ++jj)
#pragma unroll
            for (int d = 0; d < 4; ++d) o[jj][d] = 0.0;
#pragma unroll
        for (int jj = 0; jj < 3; ++jj)
#pragma unroll
            for (int d = 0; d < 3; ++d) {
                o[jj][d]     += l0 * p2[i][jj][d];
                o[jj][d + 1] += l1 * p2[i][jj][d];
            }
#pragma unroll
        for (int jj = 1; jj < 4; ++jj)
#pragma unroll
            for (int d = 0; d < 3; ++d) {
                o[jj][d]     += r0 * p2[i + 1][jj - 1][d];
                o[jj][d + 1] += r1 * p2[i + 1][jj - 1][d];
            }
#pragma unroll
        for (int jj = 0; jj < 4; ++jj)
#pragma unroll
            for (int d = 0; d < 4; ++d) p3[i][jj][d] = o[jj][d];
    }
    __syncthreads();

    // Q_j monomial; vmax
    if (tid < NJ) {
        int j = tid;
        double bb[4] = {0.0, 0.0, 0.0, 0.0};
        int ilo = (j - 3 < 0) ? 0 : j - 3;
        int ihi = (j < C_DIM - 1) ? j : C_DIM - 1;
        for (int i = ilo; i <= ihi; ++i) {
            int jj = j - i;
            double ci = sc[i];
#pragma unroll
            for (int d = 0; d < 4; ++d) bb[d] += ci * p3[i][jj][d];
        }
#pragma unroll
        for (int d = 0; d < 4; ++d) qm[j][d] = bb[d];
        vmax[j] = fmaxf(kf[j], kf[j + 1]);
    }

    // stable rank sort of the 68 knots
    if (tid < T_DIM) {
        float v = kf[tid];
        int r = 0;
        for (int i = 0; i < T_DIM; ++i) {
            float w = kf[i];
            r += (w < v) || (w == v && i < tid);
        }
        skf[r] = v;
    }
    __syncthreads();

    // distinct flags + inclusive int scan (7 steps)
    if (tid < T_DIM)
        dfl[tid] = (tid == T_DIM - 1) || (skf[tid + 1] != skf[tid]);
    __syncthreads();
    for (int stp = 1; stp < T_DIM; stp <<= 1) {
        int tmp = 0;
        bool act = (tid < T_DIM) && (tid >= stp);
        if (act) tmp = dfl[tid - stp];
        __syncthreads();
        if (act) dfl[tid] += tmp;
        __syncthreads();
    }
    if (tid < T_DIM) {
        bool last = (tid == T_DIM - 1) || (skf[tid + 1] != skf[tid]);
        if (last) dval[dfl[tid] - 1] = skf[tid];
    }
    __syncthreads();
    const int D = dfl[T_DIM - 1];       // distinct knot values, <= 68

    // prefix poly: 4 threads per m, j strided mod 4, shuffle-reduced.
    {
        const int g    = tid & 3;
        const int mloc = tid >> 2;           // 0..63
#pragma unroll
        for (int pass = 0; pass < 2; ++pass) {
            const int  m      = pass * 64 + mloc;
            const bool active = (m > 0) && (m <= D);
            const float X     = active ? dval[m - 1] : 0.0f;
            double bb[4] = {0.0, 0.0, 0.0, 0.0};
            for (int j = g; j < NJ; j += 4) {
                const double w = (active && (kf[j] <= X) && (vmax[j] > X)) ? 1.0 : 0.0;
#pragma unroll
                for (int d = 0; d < 4; ++d) bb[d] += w * qm[j][d];
            }
#pragma unroll
            for (int d = 0; d < 4; ++d)
                bb[d] += __shfl_xor_sync(0xFFFFFFFFu, bb[d], 1);
#pragma unroll
            for (int d = 0; d < 4; ++d)
                bb[d] += __shfl_xor_sync(0xFFFFFFFFu, bb[d], 2);

            if (g == 0 && m < NPFD) {
                float4 oc = make_float4(0.f, 0.f, 0.f, 0.f);
                if (active) {
                    double tc = (double)X;
#pragma unroll
                    for (int p = 0; p < 3; ++p)
#pragma unroll
                        for (int d = 2; d >= 0; --d)
                            if (d >= p) bb[d] += tc * bb[d + 1];
                    oc = make_float4((float)bb[0], (float)bb[1],
                                     (float)bb[2], (float)bb[3]);
                }
                g_CT[m][s] = oc;
            }
        }
    }
    // padded distinct breakpoints
    if (tid < NTHD) {
        float v;
        if (tid == 0)      v = -CUDART_INF_F;
        else if (tid <= D) v = dval[tid - 1];
        else               v = CUDART_INF_F;
        g_thT[tid][s] = v;
    }
    // bucket table: btT[b][s] = #{breakpoints < edge_b}; edge_0 = -INF
    for (int b = tid; b < NB; b += blockDim.x) {
        int cnt = 0;
        if (b > 0) {
            float edge = -4.0f + (float)b * (1.0f / 64.0f);   // exact in fp32
            for (int i = 0; i < D; ++i) cnt += (dval[i] < edge);
        }
        g_btT[b][s] = (uint8_t)cnt;
    }
}

// ---------------------------------------------------------------------------
// Main kernel (unchanged from R11): transposed conflict-free smem tables,
// bucket + 6 probes, depth-2 x prefetch, badmask + cold fixup.
// ---------------------------------------------------------------------------
extern __shared__ float dynsmem[];

__global__ __launch_bounds__(1024, 2)
void bspline_main_kernel(const float* __restrict__ x,
                         float* __restrict__ out, int B) {
    float*    sT = dynsmem;                         // [NTHD][32] floats
    float4*   sC = (float4*)(dynsmem + NTHD * 32);  // [NPFD][32] float4
    uint32_t* sB = (uint32_t*)(sC + NPFD * 32);     // [NB][32] bytes as words

    const int tid   = threadIdx.x;
    const int sBase = blockIdx.y * 32;

    for (int i = tid; i < NTHD * 32; i += 1024) {
        int k = i >> 5, sp = i & 31;
        sT[k * 32 + sp] = g_thT[k][sBase + sp];          // coalesced
    }
    for (int i = tid; i < NPFD * 32; i += 1024) {
        int k = i >> 5, sp = i & 31;
        sC[k * 32 + sp] = g_CT[k][sBase + sp];           // coalesced
    }
    for (int i = tid; i < NB * 8; i += 1024) {
        int b = i >> 3, w = i & 7;
        sB[b * 8 + w] = ((const uint32_t*)&g_btT[b][sBase])[w];
    }
    __syncthreads();

    const int lane = tid & 31;
    const int warp = tid >> 5;
    const float*   tl  = sT + lane;                  // tl[m*32], conflict-free
    const float4*  cl  = sC + lane;                  // cl[m*32], conflict-free
    const uint8_t* btl = (const uint8_t*)sB + lane;  // btl[b*32]
    const int col = sBase + lane;
    const int wstride = gridDim.x * 32;

    const int rstart = blockIdx.x * 32 + warp;
    int r0 = rstart;
    int r1 = r0 + wstride;
    int r2 = r1 + wstride;
    float x0 = x[r0 * N_SPLINES + col];
    float x1c = 0.0f;
    if (r1 < B) x1c = x[r1 * N_SPLINES + col];

    unsigned badmask = 0;
    int iter = 0;

    while (true) {
        float x2c = 0.0f;
        if (r2 < B) x2c = x[r2 * N_SPLINES + col];       // depth-2 prefetch

        int b = __float2int_rz(fmaf(x0, 64.0f, 256.0f)); // (x+4)*64
        b = min(max(b, 0), NB - 1);
        const int m0 = (int)btl[b * 32];

        const int mb = m0 * 32;
        const float q0 = tl[mb];
        const float q1 = tl[mb + 32];
        const float q2 = tl[mb + 64];
        const float q3 = tl[mb + 96];
        const float q4 = tl[mb + 128];
        const float q5 = tl[mb + 160];

        const int cnt = (q1 <= x0) + (q2 <= x0) + (q3 <= x0) + (q4 <= x0);
        const unsigned bad = ((q0 > x0) | (q5 <= x0)) ? 1u : 0u;
        const int m = m0 + cnt;

        const float  v   = tl[m * 32];                   // conflict-free reload
        const float  ctr = (m > 0) ? v : 0.0f;           // m=0 poly is zero
        const float4 cf  = cl[m * 32];
        const float  u   = x0 - ctr;
        out[r0 * N_SPLINES + col] =
            fmaf(fmaf(fmaf(cf.w, u, cf.z), u, cf.y), u, cf.x);

        badmask |= bad << iter;

        if (r1 >= B) break;
        r0 = r1; x0 = x1c;
        r1 = r2; x1c = x2c;
        r2 += wstride;
        ++iter;
    }

    // Cold exact fixup for flagged rows
    if (badmask) {
        while (badmask) {
            const int i = __ffs(badmask) - 1;
            badmask &= badmask - 1;
            const int r = rstart + i * wstride;
            const float xw = x[r * N_SPLINES + col];

            int b = __float2int_rz(fmaf(xw, 64.0f, 256.0f));
            b = min(max(b, 0), NB - 1);
            int m = (int)btl[b * 32];
            while (tl[m * 32] > xw) --m;              // -INF sentinel terminates
            while (tl[(m + 1) * 32] <= xw) ++m;       // +INF sentinels terminate

            const float  vv  = tl[m * 32];
            const float  ctr = (m > 0) ? vv : 0.0f;
            const float4 cf  = cl[m * 32];
            const float  u   = xw - ctr;
            out[r * N_SPLINES + col] =
                fmaf(fmaf(fmaf(cf.w, u, cf.z), u, cf.y), u, cf.x);
        }
    }
}

// ---------------------------------------------------------------------------
extern "C" void kernel_launch(void* const* d_in, const int* in_sizes, int n_in,
                              void* d_out, int out_size) {
    const float* x = (const float*)d_in[0];   // [B, 64]
    const float* t = (const float*)d_in[1];   // [64, 68]
    const float* c = (const float*)d_in[2];   // [64, 64]
    float* out = (float*)d_out;               // [B, 64]

    const int B = in_sizes[0] / N_SPLINES;    // 65536

    precompute_kernel<<<N_SPLINES, 256>>>(t, c);

    const size_t smemSz = (size_t)(NTHD * 32) * 4      // sT   9600
                        + (size_t)(NPFD * 32) * 16     // sC  36352
                        + (size_t)NB * 32;             // sB  16384  => 62336 B
    cudaFuncSetAttribute(bspline_main_kernel,
                         cudaFuncAttributeMaxDynamicSharedMemorySize, (int)smemSz);

    dim3 grid(148, 2);
    bspline_main_kernel<<<grid, 1024, smemSz>>>(x, out, B);
}

// round 15
// speedup vs baseline: 1.8947x; 1.8947x over previous
#include <cuda_runtime.h>
#include <cstdint>
#include <math_constants.h>

#define N_SPLINES 64
#define C_DIM     64
#define T_DIM     68
#define NJ        67
#define NTH       134          // raw thresholds
#define DMAX      68           // distinct thresholds are knot values => D <= 68
#define NTHD      75           // T array: [0]=-INF, [1..D], [D+1..74]=+INF
#define NPFD      71           // prefix polys m = 0..70 (m <= 68 used)
#define NB        512          // buckets, width 1/64 over [-4,4)

// Precomputed tables, TRANSPOSED in gmem for coalesced smem fill
__device__ float   g_thT[NTHD][N_SPLINES];
__device__ float4  g_CT [NPFD][N_SPLINES];
__device__ uint8_t g_btT[NB][N_SPLINES];

// ---------------------------------------------------------------------------
// Precompute (fp64) — R10-proven structure: level-parallel basis build,
// 134-threshold rank sort, dedup via int scan, per-slot gather (<=3 adds),
// 7-step fp64 scan over <=68 distinct slots, Taylor-center, bucket table.
// ---------------------------------------------------------------------------
__device__ __forceinline__ double sinv(double den) {
    return den == 0.0 ? 0.0 : 1.0 / den;
}

__global__ void precompute_kernel(const float* __restrict__ t,
                                  const float* __restrict__ c) {
    const int s   = blockIdx.x;
    const int tid = threadIdx.x;

    __shared__ double st[T_DIM];
    __shared__ double sc[C_DIM];
    __shared__ double inv1[67], inv2[66], inv3[65];
    __shared__ double p1[66][2][2];
    __shared__ double p2[65][3][3];
    __shared__ double p3[64][4][4];
    __shared__ double qm[NJ][4];
    __shared__ float  thr[NTH];
    __shared__ float  sth[NTH];
    __shared__ int    sidx[NTH];
    __shared__ int    flg[NTH];
    __shared__ float  dval[NTH];
    __shared__ int    dmap[NTH];
    __shared__ double svd[DMAX][4];    // per-distinct-slot sums -> prefix

    if (tid < T_DIM) st[tid] = (double)t[s * T_DIM + tid];
    if (tid < C_DIM) sc[tid] = (double)c[s * C_DIM + tid];
    __syncthreads();

    // L0: reciprocal gaps
    if (tid < 67) inv1[tid] = sinv(st[tid + 1] - st[tid]);
    else if (tid < 133) { int a = tid - 67; inv2[a] = sinv(st[a + 2] - st[a]); }
    else if (tid < 198) { int a = tid - 133; inv3[a] = sinv(st[a + 3] - st[a]); }
    __syncthreads();

    // L1
    if (tid < 66) {
        int a = tid;
        p1[a][0][0] = -st[a] * inv1[a];        p1[a][0][1] = inv1[a];
        p1[a][1][0] = st[a + 2] * inv1[a + 1]; p1[a][1][1] = -inv1[a + 1];
    }
    __syncthreads();

    // L2
    if (tid < 65) {
        int a = tid;
        double l0 = -st[a] * inv2[a],        l1 = inv2[a];
        double r0 = st[a + 3] * inv2[a + 1], r1 = -inv2[a + 1];
        double o[3][3];
#pragma unroll
        for (int jj = 0; jj < 3; ++jj)
#pragma unroll
            for (int d = 0; d < 3; ++d) o[jj][d] = 0.0;
#pragma unroll
        for (int jj = 0; jj < 2; ++jj)
#pragma unroll
            for (int d = 0; d < 2; ++d) {
                o[jj][d]     += l0 * p1[a][jj][d];
                o[jj][d + 1] += l1 * p1[a][jj][d];
            }
#pragma unroll
        for (int jj = 1; jj < 3; ++jj)
#pragma unroll
            for (int d = 0; d < 2; ++d) {
                o[jj][d]     += r0 * p1[a + 1][jj - 1][d];
                o[jj][d + 1] += r1 * p1[a + 1][jj - 1][d];
            }
#pragma unroll
        for (int jj = 0; jj < 3; ++jj)
#pragma unroll
            for (int d = 0; d < 3; ++d) p2[a][jj][d] = o[jj][d];
    }
    __syncthreads();

    // L3
    if (tid < 64) {
        int i = tid;
        double l0 = -st[i] * inv3[i],        l1 = inv3[i];
        double r0 = st[i + 4] * inv3[i + 1], r1 = -inv3[i + 1];
        double o[4][4];
#pragma unroll
        for (int jj = 0; jj < 4; ++jj)
#pragma unroll
            for (int d = 0; d < 4; ++d) o[jj][d] = 0.0;
#pragma unroll
        for (int jj = 0; jj < 3; ++jj)
#pragma unroll
            for (int d = 0; d < 3; ++d) {
                o[jj][d]     += l0 * p2[i][jj][d];
                o[jj][d + 1] += l1 * p2[i][jj][d];
            }
#pragma unroll
        for (int jj = 1; jj < 4; ++jj)
#pragma unroll
            for (int d = 0; d < 3; ++d) {
                o[jj][d]     += r0 * p2[i + 1][jj - 1][d];
                o[jj][d + 1] += r1 * p2[i + 1][jj - 1][d];
            }
#pragma unroll
        for (int jj = 0; jj < 4; ++jj)
#pragma unroll
            for (int d = 0; d < 4; ++d) p3[i][jj][d] = o[jj][d];
    }
    __syncthreads();

    // Q_j monomial
    if (tid < NJ) {
        int j = tid;
        double bb[4] = {0.0, 0.0, 0.0, 0.0};
        int ilo = (j - 3 < 0) ? 0 : j - 3;
        int ihi = (j < C_DIM - 1) ? j : C_DIM - 1;
        for (int i = ilo; i <= ihi; ++i) {
            int jj = j - i;
            double ci = sc[i];
#pragma unroll
            for (int d = 0; d < 4; ++d) bb[d] += ci * p3[i][jj][d];
        }
#pragma unroll
        for (int d = 0; d < 4; ++d) qm[j][d] = bb[d];
    }

    // raw thresholds
    if (tid < NTH) {
        if (tid < NJ) thr[tid] = t[s * T_DIM + tid];
        else {
            int j = tid - NJ;
            thr[tid] = fmaxf(t[s * T_DIM + j], t[s * T_DIM + j + 1]);
        }
    }
    __syncthreads();

    // stable rank sort of raw thresholds
    if (tid < NTH) {
        float v = thr[tid];
        int r = 0;
        for (int i = 0; i < NTH; ++i) {
            float w = thr[i];
            r += (w < v) || (w == v && i < tid);
        }
        sth[r] = v;
        sidx[r] = tid;
    }
    __syncthreads();

    // dedup flags + int scan
    if (tid < NTH)
        flg[tid] = (tid == NTH - 1) || (sth[tid + 1] != sth[tid]);
    __syncthreads();
    for (int stp = 1; stp < NTH; stp <<= 1) {
        int tmp = 0;
        bool act = (tid < NTH) && (tid >= stp);
        if (act) tmp = flg[tid - stp];
        __syncthreads();
        if (act) flg[tid] += tmp;
        __syncthreads();
    }
    if (tid < NTH) {
        bool last = (tid == NTH - 1) || (sth[tid + 1] != sth[tid]);
        if (last) {
            int r = flg[tid] - 1;   // distinct slot index
            dval[r] = sth[tid];
            dmap[r] = tid;          // last raw position of this value
        }
    }
    __syncthreads();
    const int D = flg[NTH - 1];     // <= 68 (thresholds are knot values)

    // scatter raw signed pieces into distinct slots (<=3 per slot)
    if (tid < D) {
        int lo = (tid == 0) ? 0 : dmap[tid - 1] + 1;
        int hi = dmap[tid];
        double acc[4] = {0.0, 0.0, 0.0, 0.0};
        for (int i = lo; i <= hi; ++i) {
            int k = sidx[i];
            int p = (k < NJ) ? k : k - NJ;
            double sgn = (k < NJ) ? 1.0 : -1.0;
#pragma unroll
            for (int d = 0; d < 4; ++d) acc[d] += sgn * qm[p][d];
        }
#pragma unroll
        for (int d = 0; d < 4; ++d) svd[tid][d] = acc[d];
    }
    __syncthreads();

    // inclusive fp64 scan over D slots (7 steps)
    for (int stp = 1; stp < DMAX; stp <<= 1) {
        double tmp[4] = {0.0, 0.0, 0.0, 0.0};
        bool act = (tid < D) && (tid >= stp);
        if (act) {
#pragma unroll
            for (int d = 0; d < 4; ++d) tmp[d] = svd[tid - stp][d];
        }
        __syncthreads();
        if (act) {
#pragma unroll
            for (int d = 0; d < 4; ++d) svd[tid][d] += tmp[d];
        }
        __syncthreads();
    }

    // Taylor-center prefix poly m at dval[m-1]; write TRANSPOSED
    if (tid < NPFD) {
        int m = tid;
        float4 oc = make_float4(0.f, 0.f, 0.f, 0.f);
        if (m > 0 && m <= D) {
            double bb[4];
#pragma unroll
            for (int d = 0; d < 4; ++d) bb[d] = svd[m - 1][d];
            double tc = (double)dval[m - 1];
#pragma unroll
            for (int pass = 0; pass < 3; ++pass)
#pragma unroll
                for (int d = 2; d >= 0; --d)
                    if (d >= pass) bb[d] += tc * bb[d + 1];
            oc = make_float4((float)bb[0], (float)bb[1], (float)bb[2], (float)bb[3]);
        }
        g_CT[m][s] = oc;
    }
    // padded distinct thresholds (TRANSPOSED)
    if (tid < NTHD) {
        float v;
        if (tid == 0)      v = -CUDART_INF_F;
        else if (tid <= D) v = dval[tid - 1];
        else               v = CUDART_INF_F;
        g_thT[tid][s] = v;
    }
    // bucket table (transposed): btT[b][s] = #{distinct th < edge_b}
    for (int b = tid; b < NB; b += blockDim.x) {
        int cnt = 0;
        if (b > 0) {
            float edge = -4.0f + (float)b * (1.0f / 64.0f);   // exact in fp32
            for (int i = 0; i < D; ++i) cnt += (dval[i] < edge);
        }
        g_btT[b][s] = (uint8_t)cnt;
    }
}

// ---------------------------------------------------------------------------
// Main kernel (R11-proven, unchanged): transposed conflict-free smem tables,
// bucket + 6 probes, depth-2 x prefetch, badmask + cold fixup.
// ---------------------------------------------------------------------------
extern __shared__ float dynsmem[];

__global__ __launch_bounds__(1024, 2)
void bspline_main_kernel(const float* __restrict__ x,
                         float* __restrict__ out, int B) {
    float*    sT = dynsmem;                         // [NTHD][32] floats
    float4*   sC = (float4*)(dynsmem + NTHD * 32);  // [NPFD][32] float4
    uint32_t* sB = (uint32_t*)(sC + NPFD * 32);     // [NB][32] bytes as words

    const int tid   = threadIdx.x;
    const int sBase = blockIdx.y * 32;

    for (int i = tid; i < NTHD * 32; i += 1024) {
        int k = i >> 5, sp = i & 31;
        sT[k * 32 + sp] = g_thT[k][sBase + sp];          // coalesced
    }
    for (int i = tid; i < NPFD * 32; i += 1024) {
        int k = i >> 5, sp = i & 31;
        sC[k * 32 + sp] = g_CT[k][sBase + sp];           // coalesced
    }
    for (int i = tid; i < NB * 8; i += 1024) {
        int b = i >> 3, w = i & 7;
        sB[b * 8 + w] = ((const uint32_t*)&g_btT[b][sBase])[w];
    }
    __syncthreads();

    const int lane = tid & 31;
    const int warp = tid >> 5;
    const float*   tl  = sT + lane;                  // tl[m*32], conflict-free
    const float4*  cl  = sC + lane;                  // cl[m*32], conflict-free
    const uint8_t* btl = (const uint8_t*)sB + lane;  // btl[b*32]
    const int col = sBase + lane;
    const int wstride = gridDim.x * 32;

    const int rstart = blockIdx.x * 32 + warp;
    int r0 = rstart;
    int r1 = r0 + wstride;
    int r2 = r1 + wstride;
    float x0 = x[r0 * N_SPLINES + col];
    float x1c = 0.0f;
    if (r1 < B) x1c = x[r1 * N_SPLINES + col];

    unsigned badmask = 0;
    int iter = 0;

    while (true) {
        float x2c = 0.0f;
        if (r2 < B) x2c = x[r2 * N_SPLINES + col];       // depth-2 prefetch

        int b = __float2int_rz(fmaf(x0, 64.0f, 256.0f)); // (x+4)*64
        b = min(max(b, 0), NB - 1);
        const int m0 = (int)btl[b * 32];

        const int mb = m0 * 32;
        const float q0 = tl[mb];
        const float q1 = tl[mb + 32];
        const float q2 = tl[mb + 64];
        const float q3 = tl[mb + 96];
        const float q4 = tl[mb + 128];
        const float q5 = tl[mb + 160];

        const int cnt = (q1 <= x0) + (q2 <= x0) + (q3 <= x0) + (q4 <= x0);
        const unsigned bad = ((q0 > x0) | (q5 <= x0)) ? 1u : 0u;
        const int m = m0 + cnt;

        const float  v   = tl[m * 32];                   // conflict-free reload
        const float  ctr = (m > 0) ? v : 0.0f;           // m=0 poly is zero
        const float4 cf  = cl[m * 32];
        const float  u   = x0 - ctr;
        out[r0 * N_SPLINES + col] =
            fmaf(fmaf(fmaf(cf.w, u, cf.z), u, cf.y), u, cf.x);

        badmask |= bad << iter;

        if (r1 >= B) break;
        r0 = r1; x0 = x1c;
        r1 = r2; x1c = x2c;
        r2 += wstride;
        ++iter;
    }

    // Cold exact fixup for flagged rows
    if (badmask) {
        while (badmask) {
            const int i = __ffs(badmask) - 1;
            badmask &= badmask - 1;
            const int r = rstart + i * wstride;
            const float xw = x[r * N_SPLINES + col];

            int b = __float2int_rz(fmaf(xw, 64.0f, 256.0f));
            b = min(max(b, 0), NB - 1);
            int m = (int)btl[b * 32];
            while (tl[m * 32] > xw) --m;              // -INF sentinel terminates
            while (tl[(m + 1) * 32] <= xw) ++m;       // +INF sentinels terminate

            const float  vv  = tl[m * 32];
            const float  ctr = (m > 0) ? vv : 0.0f;
            const float4 cf  = cl[m * 32];
            const float  u   = xw - ctr;
            out[r * N_SPLINES + col] =
                fmaf(fmaf(fmaf(cf.w, u, cf.z), u, cf.y), u, cf.x);
        }
    }
}

// ---------------------------------------------------------------------------
extern "C" void kernel_launch(void* const* d_in, const int* in_sizes, int n_in,
                              void* d_out, int out_size) {
    const float* x = (const float*)d_in[0];   // [B, 64]
    const float* t = (const float*)d_in[1];   // [64, 68]
    const float* c = (const float*)d_in[2];   // [64, 64]
    float* out = (float*)d_out;               // [B, 64]

    const int B = in_sizes[0] / N_SPLINES;    // 65536

    precompute_kernel<<<N_SPLINES, 256>>>(t, c);

    const size_t smemSz = (size_t)(NTHD * 32) * 4      // sT   9600
                        + (size_t)(NPFD * 32) * 16     // sC  36352
                        + (size_t)NB * 32;             // sB  16384  => 62336 B
    cudaFuncSetAttribute(bspline_main_kernel,
                         cudaFuncAttributeMaxDynamicSharedMemorySize, (int)smemSz);

    dim3 grid(148, 2);
    bspline_main_kernel<<<grid, 1024, smemSz>>>(x, out, B);
}

// round 16
// speedup vs baseline: 1.8988x; 1.0022x over previous
#include <cuda_runtime.h>
#include <cstdint>
#include <math_constants.h>

#define N_SPLINES 64
#define C_DIM     64
#define T_DIM     68
#define NJ        67
#define NTH       134          // raw thresholds
#define DMAX      68           // distinct thresholds are knot values => D <= 68
#define NTHD      75           // T array: [0]=-INF, [1..D], [D+1..74]=+INF
#define NPFD      71           // prefix polys m = 0..70 (m <= 68 used)
#define NB        512          // buckets, width 1/64 over [-4,4)

// Precomputed tables, TRANSPOSED in gmem for coalesced smem fill
__device__ float   g_thT[NTHD][N_SPLINES];
__device__ float4  g_CT [NPFD][N_SPLINES];
__device__ uint8_t g_btT[NB][N_SPLINES];

// ---------------------------------------------------------------------------
// Precompute (fp64) — R10-proven structure (unchanged from R15).
// ---------------------------------------------------------------------------
__device__ __forceinline__ double sinv(double den) {
    return den == 0.0 ? 0.0 : 1.0 / den;
}

__global__ void precompute_kernel(const float* __restrict__ t,
                                  const float* __restrict__ c) {
    const int s   = blockIdx.x;
    const int tid = threadIdx.x;

    __shared__ double st[T_DIM];
    __shared__ double sc[C_DIM];
    __shared__ double inv1[67], inv2[66], inv3[65];
    __shared__ double p1[66][2][2];
    __shared__ double p2[65][3][3];
    __shared__ double p3[64][4][4];
    __shared__ double qm[NJ][4];
    __shared__ float  thr[NTH];
    __shared__ float  sth[NTH];
    __shared__ int    sidx[NTH];
    __shared__ int    flg[NTH];
    __shared__ float  dval[NTH];
    __shared__ int    dmap[NTH];
    __shared__ double svd[DMAX][4];    // per-distinct-slot sums -> prefix

    if (tid < T_DIM) st[tid] = (double)t[s * T_DIM + tid];
    if (tid < C_DIM) sc[tid] = (double)c[s * C_DIM + tid];
    __syncthreads();

    // L0: reciprocal gaps
    if (tid < 67) inv1[tid] = sinv(st[tid + 1] - st[tid]);
    else if (tid < 133) { int a = tid - 67; inv2[a] = sinv(st[a + 2] - st[a]); }
    else if (tid < 198) { int a = tid - 133; inv3[a] = sinv(st[a + 3] - st[a]); }
    __syncthreads();

    // L1
    if (tid < 66) {
        int a = tid;
        p1[a][0][0] = -st[a] * inv1[a];        p1[a][0][1] = inv1[a];
        p1[a][1][0] = st[a + 2] * inv1[a + 1]; p1[a][1][1] = -inv1[a + 1];
    }
    __syncthreads();

    // L2
    if (tid < 65) {
        int a = tid;
        double l0 = -st[a] * inv2[a],        l1 = inv2[a];
        double r0 = st[a + 3] * inv2[a + 1], r1 = -inv2[a + 1];
        double o[3][3];
#pragma unroll
        for (int jj = 0; jj < 3; ++jj)
#pragma unroll
            for (int d = 0; d < 3; ++d) o[jj][d] = 0.0;
#pragma unroll
        for (int jj = 0; jj < 2; ++jj)
#pragma unroll
            for (int d = 0; d < 2; ++d) {
                o[jj][d]     += l0 * p1[a][jj][d];
                o[jj][d + 1] += l1 * p1[a][jj][d];
            }
#pragma unroll
        for (int jj = 1; jj < 3; ++jj)
#pragma unroll
            for (int d = 0; d < 2; ++d) {
                o[jj][d]     += r0 * p1[a + 1][jj - 1][d];
                o[jj][d + 1] += r1 * p1[a + 1][jj - 1][d];
            }
#pragma unroll
        for (int jj = 0; jj < 3; ++jj)
#pragma unroll
            for (int d = 0; d < 3; ++d) p2[a][jj][d] = o[jj][d];
    }
    __syncthreads();

    // L3
    if (tid < 64) {
        int i = tid;
        double l0 = -st[i] * inv3[i],        l1 = inv3[i];
        double r0 = st[i + 4] * inv3[i + 1], r1 = -inv3[i + 1];
        double o[4][4];
#pragma unroll
        for (int jj = 0; jj < 4; ++jj)
#pragma unroll
            for (int d = 0; d < 4; ++d) o[jj][d] = 0.0;
#pragma unroll
        for (int jj = 0; jj < 3; ++jj)
#pragma unroll
            for (int d = 0; d < 3; ++d) {
                o[jj][d]     += l0 * p2[i][jj][d];
                o[jj][d + 1] += l1 * p2[i][jj][d];
            }
#pragma unroll
        for (int jj = 1; jj < 4; ++jj)
#pragma unroll
            for (int d = 0; d < 3; ++d) {
                o[jj][d]     += r0 * p2[i + 1][jj - 1][d];
                o[jj][d + 1] += r1 * p2[i + 1][jj - 1][d];
            }
#pragma unroll
        for (int jj = 0; jj < 4; ++jj)
#pragma unroll
            for (int d = 0; d < 4; ++d) p3[i][jj][d] = o[jj][d];
    }
    __syncthreads();

    // Q_j monomial
    if (tid < NJ) {
        int j = tid;
        double bb[4] = {0.0, 0.0, 0.0, 0.0};
        int ilo = (j - 3 < 0) ? 0 : j - 3;
        int ihi = (j < C_DIM - 1) ? j : C_DIM - 1;
        for (int i = ilo; i <= ihi; ++i) {
            int jj = j - i;
            double ci = sc[i];
#pragma unroll
            for (int d = 0; d < 4; ++d) bb[d] += ci * p3[i][jj][d];
        }
#pragma unroll
        for (int d = 0; d < 4; ++d) qm[j][d] = bb[d];
    }

    // raw thresholds
    if (tid < NTH) {
        if (tid < NJ) thr[tid] = t[s * T_DIM + tid];
        else {
            int j = tid - NJ;
            thr[tid] = fmaxf(t[s * T_DIM + j], t[s * T_DIM + j + 1]);
        }
    }
    __syncthreads();

    // stable rank sort of raw thresholds
    if (tid < NTH) {
        float v = thr[tid];
        int r = 0;
        for (int i = 0; i < NTH; ++i) {
            float w = thr[i];
            r += (w < v) || (w == v && i < tid);
        }
        sth[r] = v;
        sidx[r] = tid;
    }
    __syncthreads();

    // dedup flags + int scan
    if (tid < NTH)
        flg[tid] = (tid == NTH - 1) || (sth[tid + 1] != sth[tid]);
    __syncthreads();
    for (int stp = 1; stp < NTH; stp <<= 1) {
        int tmp = 0;
        bool act = (tid < NTH) && (tid >= stp);
        if (act) tmp = flg[tid - stp];
        __syncthreads();
        if (act) flg[tid] += tmp;
        __syncthreads();
    }
    if (tid < NTH) {
        bool last = (tid == NTH - 1) || (sth[tid + 1] != sth[tid]);
        if (last) {
            int r = flg[tid] - 1;   // distinct slot index
            dval[r] = sth[tid];
            dmap[r] = tid;          // last raw position of this value
        }
    }
    __syncthreads();
    const int D = flg[NTH - 1];     // <= 68 (thresholds are knot values)

    // scatter raw signed pieces into distinct slots (<=3 per slot)
    if (tid < D) {
        int lo = (tid == 0) ? 0 : dmap[tid - 1] + 1;
        int hi = dmap[tid];
        double acc[4] = {0.0, 0.0, 0.0, 0.0};
        for (int i = lo; i <= hi; ++i) {
            int k = sidx[i];
            int p = (k < NJ) ? k : k - NJ;
            double sgn = (k < NJ) ? 1.0 : -1.0;
#pragma unroll
            for (int d = 0; d < 4; ++d) acc[d] += sgn * qm[p][d];
        }
#pragma unroll
        for (int d = 0; d < 4; ++d) svd[tid][d] = acc[d];
    }
    __syncthreads();

    // inclusive fp64 scan over D slots (7 steps)
    for (int stp = 1; stp < DMAX; stp <<= 1) {
        double tmp[4] = {0.0, 0.0, 0.0, 0.0};
        bool act = (tid < D) && (tid >= stp);
        if (act) {
#pragma unroll
            for (int d = 0; d < 4; ++d) tmp[d] = svd[tid - stp][d];
        }
        __syncthreads();
        if (act) {
#pragma unroll
            for (int d = 0; d < 4; ++d) svd[tid][d] += tmp[d];
        }
        __syncthreads();
    }

    // Taylor-center prefix poly m at dval[m-1]; write TRANSPOSED
    if (tid < NPFD) {
        int m = tid;
        float4 oc = make_float4(0.f, 0.f, 0.f, 0.f);
        if (m > 0 && m <= D) {
            double bb[4];
#pragma unroll
            for (int d = 0; d < 4; ++d) bb[d] = svd[m - 1][d];
            double tc = (double)dval[m - 1];
#pragma unroll
            for (int pass = 0; pass < 3; ++pass)
#pragma unroll
                for (int d = 2; d >= 0; --d)
                    if (d >= pass) bb[d] += tc * bb[d + 1];
            oc = make_float4((float)bb[0], (float)bb[1], (float)bb[2], (float)bb[3]);
        }
        g_CT[m][s] = oc;
    }
    // padded distinct thresholds (TRANSPOSED)
    if (tid < NTHD) {
        float v;
        if (tid == 0)      v = -CUDART_INF_F;
        else if (tid <= D) v = dval[tid - 1];
        else               v = CUDART_INF_F;
        g_thT[tid][s] = v;
    }
    // bucket table (transposed): btT[b][s] = #{distinct th < edge_b}
    for (int b = tid; b < NB; b += blockDim.x) {
        int cnt = 0;
        if (b > 0) {
            float edge = -4.0f + (float)b * (1.0f / 64.0f);   // exact in fp32
            for (int i = 0; i < D; ++i) cnt += (dval[i] < edge);
        }
        g_btT[b][s] = (uint8_t)cnt;
    }
}

// ---------------------------------------------------------------------------
// Main kernel: transposed conflict-free smem tables; bucket LDS pipelined one
// iteration ahead (chain = probes -> coeffs, 2 LDS levels); 5 probes;
// depth-2 x prefetch; badmask + cold fixup.
// ---------------------------------------------------------------------------
extern __shared__ float dynsmem[];

__device__ __forceinline__ int bucket_of(float xv) {
    int b = __float2int_rz(fmaf(xv, 64.0f, 256.0f));   // (x+4)*64
    return min(max(b, 0), NB - 1);
}

__global__ __launch_bounds__(1024, 2)
void bspline_main_kernel(const float* __restrict__ x,
                         float* __restrict__ out, int B) {
    float*    sT = dynsmem;                         // [NTHD][32] floats
    float4*   sC = (float4*)(dynsmem + NTHD * 32);  // [NPFD][32] float4
    uint32_t* sB = (uint32_t*)(sC + NPFD * 32);     // [NB][32] bytes as words

    const int tid   = threadIdx.x;
    const int sBase = blockIdx.y * 32;

    for (int i = tid; i < NTHD * 32; i += 1024) {
        int k = i >> 5, sp = i & 31;
        sT[k * 32 + sp] = g_thT[k][sBase + sp];          // coalesced
    }
    for (int i = tid; i < NPFD * 32; i += 1024) {
        int k = i >> 5, sp = i & 31;
        sC[k * 32 + sp] = g_CT[k][sBase + sp];           // coalesced
    }
    for (int i = tid; i < NB * 8; i += 1024) {
        int b = i >> 3, w = i & 7;
        sB[b * 8 + w] = ((const uint32_t*)&g_btT[b][sBase])[w];
    }
    __syncthreads();

    const int lane = tid & 31;
    const int warp = tid >> 5;
    const float*   tl  = sT + lane;                  // tl[m*32], conflict-free
    const float4*  cl  = sC + lane;                  // cl[m*32], conflict-free
    const uint8_t* btl = (const uint8_t*)sB + lane;  // btl[b*32]
    const int col = sBase + lane;
    const int wstride = gridDim.x * 32;

    const int rstart = blockIdx.x * 32 + warp;
    int r0 = rstart;
    int r1 = r0 + wstride;
    int r2 = r1 + wstride;
    float x0 = x[r0 * N_SPLINES + col];
    float x1c = 0.0f;
    if (r1 < B) x1c = x[r1 * N_SPLINES + col];

    // prologue: bucket lookup for the first row
    int m0 = (int)btl[bucket_of(x0) * 32];

    unsigned badmask = 0;
    int iter = 0;

    while (true) {
        float x2c = 0.0f;
        if (r2 < B) x2c = x[r2 * N_SPLINES + col];       // depth-2 LDG prefetch

        // pipelined bucket lookup for the NEXT row (x1c=0 dummy is safe: clamped)
        const int m0n = (int)btl[bucket_of(x1c) * 32];

        const int mb = m0 * 32;
        const float q0 = tl[mb];
        const float q1 = tl[mb + 32];
        const float q2 = tl[mb + 64];
        const float q3 = tl[mb + 96];
        const float q4 = tl[mb + 128];

        const int cnt = (q1 <= x0) + (q2 <= x0) + (q3 <= x0);
        const unsigned bad = ((q0 > x0) | (q4 <= x0)) ? 1u : 0u;
        const int m = m0 + cnt;

        const float  v   = tl[m * 32];                   // conflict-free reload
        const float  ctr = (m > 0) ? v : 0.0f;           // m=0 poly is zero
        const float4 cf  = cl[m * 32];
        const float  u   = x0 - ctr;
        out[r0 * N_SPLINES + col] =
            fmaf(fmaf(fmaf(cf.w, u, cf.z), u, cf.y), u, cf.x);

        badmask |= bad << iter;

        if (r1 >= B) break;
        r0 = r1; x0 = x1c;
        r1 = r2; x1c = x2c;
        r2 += wstride;
        m0 = m0n;
        ++iter;
    }

    // Cold exact fixup for flagged rows
    if (badmask) {
        while (badmask) {
            const int i = __ffs(badmask) - 1;
            badmask &= badmask - 1;
            const int r = rstart + i * wstride;
            const float xw = x[r * N_SPLINES + col];

            int m = (int)btl[bucket_of(xw) * 32];
            while (tl[m * 32] > xw) --m;              // -INF sentinel terminates
            while (tl[(m + 1) * 32] <= xw) ++m;       // +INF sentinels terminate

            const float  vv  = tl[m * 32];
            const float  ctr = (m > 0) ? vv : 0.0f;
            const float4 cf  = cl[m * 32];
            const float  u   = xw - ctr;
            out[r * N_SPLINES + col] =
                fmaf(fmaf(fmaf(cf.w, u, cf.z), u, cf.y), u, cf.x);
        }
    }
}

// ---------------------------------------------------------------------------
extern "C" void kernel_launch(void* const* d_in, const int* in_sizes, int n_in,
                              void* d_out, int out_size) {
    const float* x = (const float*)d_in[0];   // [B, 64]
    const float* t = (const float*)d_in[1];   // [64, 68]
    const float* c = (const float*)d_in[2];   // [64, 64]
    float* out = (float*)d_out;               // [B, 64]

    const int B = in_sizes[0] / N_SPLINES;    // 65536

    precompute_kernel<<<N_SPLINES, 256>>>(t, c);

    const size_t smemSz = (size_t)(NTHD * 32) * 4      // sT   9600
                        + (size_t)(NPFD * 32) * 16     // sC  36352
                        + (size_t)NB * 32;             // sB  16384  => 62336 B
    cudaFuncSetAttribute(bspline_main_kernel,
                         cudaFuncAttributeMaxDynamicSharedMemorySize, (int)smemSz);

    dim3 grid(148, 2);
    bspline_main_kernel<<<grid, 1024, smemSz>>>(x, out, B);
}